// round 14
// baseline (speedup 1.0000x reference)
#include <cuda_runtime.h>
#include <math.h>
#include <stdint.h>

// Shapes fixed by the problem definition.
#define Bv 4
#define Tv 2048
#define Dv 384
#define Hv 192
#define VD (Dv/4)     // 96 float4 per row
#define MROWS 32      // rows per MLP block (8 warps x 4 rows)
#define NB0 (Tv/MROWS)          // 64 batch-0 MLP blocks
#define NB13 ((Bv-1)*Tv/MROWS)  // 192 MLP blocks for batches 1..3
#define KC 16         // k-tile rows (double buffered)
#define NTILE (Dv/KC) // 24
#define GMIN (8*Tv)   // guaranteed minimum total length (MIN_DUR=8)
#define CPP 64        // output positions per copy block (32 per warp)
#define ZPB 6144      // float4 per zero block (256 thr x 24)
#define NTHR 256

// Scratch (no allocs allowed).
__device__ float g_dur[Tv];
__device__ int   g_cum[Tv];
__device__ int   g_total;
__device__ int   g_cnt;    // batch-0 completion counter  (reset by last block)
__device__ int   g_ready;  // scan-done flag              (reset by last block)
__device__ int   g_done;   // all-blocks completion count (reset by last block)

#define FMA_F32X2(d, a, b, c) \
    asm("fma.rn.f32x2 %0, %1, %2, %3;" : "=l"(d) : "l"(a), "l"(b), "l"(c))
#define PACK_DUP(out, v) \
    asm("mov.b64 %0, {%1, %1};" : "=l"(out) : "r"(v))
#define UNPACK2(lo, hi, in) \
    asm("mov.b64 {%0, %1}, %2;" : "=r"(lo), "=r"(hi) : "l"(in))

#define CP16(dst_u32, src_ptr) \
    asm volatile("cp.async.cg.shared.global [%0], [%1], 16;\n" :: "r"(dst_u32), "l"(src_ptr))
#define CP_COMMIT() asm volatile("cp.async.commit_group;\n")
#define CP_WAIT(n)  asm volatile("cp.async.wait_group %0;\n" :: "n"(n))

__device__ __forceinline__ uint32_t smem_u32(const void* p) {
    return (uint32_t)__cvta_generic_to_shared(p);
}

__device__ __forceinline__ float duration_of(float z) {
    // softplus -> clamp to MIN_DUR=8 -> round (nearest-even, matching jnp.round)
    float sp = (z > 20.f) ? z : log1pf(expf(z));
    return rintf(fmaxf(sp, 8.f));
}

// MLP for MROWS=32 rows starting at row0 (8 warps, 4 rows/warp).
// w1 streamed via cp.async double-buffered KC=16 tiles; x tile loaded once.
// Packed fma.rn.f32x2 accumulation. (Proven since R4 — unchanged.)
__device__ __forceinline__ void mlp_block(
    const float* __restrict__ x, const float* __restrict__ w1,
    const float* __restrict__ b1, const float* __restrict__ w2,
    const float* __restrict__ b2, int row0,
    float* smem, float* __restrict__ out_tail)
{
    float* s_x = smem;                 // [MROWS][Dv]   48KB
    float* s_w = smem + MROWS * Dv;    // [2][KC][Hv]   24KB

    const int tid  = threadIdx.x;
    const int lane = tid & 31;
    const int warp = tid >> 5;
    const int rb   = warp * 4;

    {
        const float4* __restrict__ xg = (const float4*)(x + (long)row0 * Dv);
        uint32_t sx = smem_u32(s_x);
#pragma unroll
        for (int i = tid; i < MROWS * Dv / 4; i += NTHR)
            CP16(sx + (uint32_t)i * 16u, xg + i);
        CP_COMMIT();
    }
    {
        const float4* __restrict__ wg = (const float4*)w1;
        uint32_t sw = smem_u32(s_w);
#pragma unroll
        for (int i = tid; i < KC * Hv / 4; i += NTHR)
            CP16(sw + (uint32_t)i * 16u, wg + i);
        CP_COMMIT();
    }

    uint64_t acc[4][3];
#pragma unroll
    for (int r = 0; r < 4; ++r)
#pragma unroll
        for (int m = 0; m < 3; ++m) acc[r][m] = 0ull;

    for (int t = 0; t < NTILE; ++t) {
        if (t + 1 < NTILE) {
            const float4* __restrict__ wg =
                (const float4*)(w1 + (long)(t + 1) * KC * Hv);
            uint32_t sw = smem_u32(s_w + ((t + 1) & 1) * KC * Hv);
#pragma unroll
            for (int i = tid; i < KC * Hv / 4; i += NTHR)
                CP16(sw + (uint32_t)i * 16u, wg + i);
            CP_COMMIT();
            CP_WAIT(1);
        } else {
            CP_WAIT(0);
        }
        __syncthreads();

        const float* wb = s_w + (t & 1) * KC * Hv;
#pragma unroll
        for (int k0 = 0; k0 < KC; k0 += 4) {
            float4 xa[4];
#pragma unroll
            for (int r = 0; r < 4; ++r)
                xa[r] = *(const float4*)(s_x + (rb + r) * Dv + t * KC + k0);
#pragma unroll
            for (int kk = 0; kk < 4; ++kk) {
                uint64_t xd[4];
#pragma unroll
                for (int r = 0; r < 4; ++r)
                    PACK_DUP(xd[r], __float_as_uint((&xa[r].x)[kk]));
#pragma unroll
                for (int m = 0; m < 3; ++m) {
                    uint64_t wv = *(const uint64_t*)(wb + (k0 + kk) * Hv
                                                     + 2 * (lane + 32 * m));
#pragma unroll
                    for (int r = 0; r < 4; ++r)
                        FMA_F32X2(acc[r][m], xd[r], wv, acc[r][m]);
                }
            }
        }
        __syncthreads();
    }

    float bz = b2[0];
    float pr[4] = {0.f, 0.f, 0.f, 0.f};
#pragma unroll
    for (int m = 0; m < 3; ++m) {
        int jp = lane + 32 * m;
        float2 bb = *(const float2*)(b1 + 2 * jp);
        float2 ww = *(const float2*)(w2 + 2 * jp);
#pragma unroll
        for (int r = 0; r < 4; ++r) {
            uint32_t lo, hi;
            UNPACK2(lo, hi, acc[r][m]);
            pr[r] += fmaxf(__uint_as_float(lo) + bb.x, 0.f) * ww.x
                   + fmaxf(__uint_as_float(hi) + bb.y, 0.f) * ww.y;
        }
    }
#pragma unroll
    for (int off = 16; off > 0; off >>= 1)
#pragma unroll
        for (int r = 0; r < 4; ++r)
            pr[r] += __shfl_xor_sync(0xffffffffu, pr[r], off);
    if (lane == 0) {
#pragma unroll
        for (int r = 0; r < 4; ++r) {
            int row = row0 + rb + r;
            float d = duration_of(pr[r] + bz);
            if (out_tail) out_tail[row] = d;
            if (row < Tv) g_dur[row] = d;
        }
    }
}

// Fused kernel. Grid layout (bid order = dispatch order) — R9/R12 proven:
//  [0, NB0)            batch-0 MLP; last finisher scans g_dur -> g_cum,
//                      g_total, then sets g_ready (fence-ordered)
//  [NB0, mlpN)         MLP for batches 1..3 (duration_pred tail only)
//  [mlpN, mlpN+nbz)    zero-fill out[b][zstart..TL][:]  (flat, contiguous)
//  [mlpN+nbz, ...)     gather-copy p in [0, zstart); waits on g_ready
//                      (dispatched ~40us in; flag set ~8us in, so no stall)
// Epilogue (all blocks): increment g_done; the final finisher copies the
// overflow [zstart, g_total) over the zeros — ordered after ALL zero/copy
// blocks, so no race; empty when g_total == GMIN — and resets replay state.
__global__ __launch_bounds__(NTHR)
void fused_kernel(const float* __restrict__ x, const float* __restrict__ w1,
                  const float* __restrict__ b1, const float* __restrict__ w2,
                  const float* __restrict__ b2, float* __restrict__ out,
                  long TL, long tail_off, long zstart, int mlpN, int nbz)
{
    extern __shared__ float smem[];
    const int tid  = threadIdx.x;
    const int lane = tid & 31;
    const int warp = tid >> 5;
    int bid = (int)blockIdx.x;
    float4* __restrict__ out4 = (float4*)out;
    const float4* __restrict__ x4 = (const float4*)x;

    if (bid < mlpN) {
        int row0 = (bid < NB0) ? bid * MROWS : Tv + (bid - NB0) * MROWS;
        mlp_block(x, w1, b1, w2, b2, row0, smem,
                  tail_off >= 0 ? out + tail_off : nullptr);
        if (bid < NB0) {
            // Batch-0 blocks: last finisher performs the scan + publishes.
            __shared__ int s_go;
            __syncthreads();
            if (tid == 0) {
                __threadfence();
                s_go = (atomicAdd(&g_cnt, 1) == NB0 - 1);
            }
            __syncthreads();
            if (s_go) {
                __threadfence();
                int* s_sum = (int*)smem;
                int loc[8]; int s = 0;
#pragma unroll
                for (int i = 0; i < 8; ++i) {
                    loc[i] = (int)g_dur[tid * 8 + i]; s += loc[i];
                }
                s_sum[tid] = s;
                __syncthreads();
#pragma unroll
                for (int off = 1; off < 256; off <<= 1) {
                    int v = (tid >= off) ? s_sum[tid - off] : 0;
                    __syncthreads();
                    s_sum[tid] += v;
                    __syncthreads();
                }
                int run = (tid > 0) ? s_sum[tid - 1] : 0;
#pragma unroll
                for (int i = 0; i < 8; ++i) {
                    run += loc[i]; g_cum[tid * 8 + i] = run;
                }
                if (tid == 255) g_total = run;
                __syncthreads();
                if (tid == 0) {
                    __threadfence();
                    atomicExch(&g_ready, 1);
                }
            }
        }
    } else if (bid < mlpN + nbz) {
        // Zero-fill: flat float4 index space over Bv slabs out[b][zstart..TL][:].
        int zb = bid - mlpN;
        unsigned S = (unsigned)((TL - zstart) * VD);   // f4 per slab
        unsigned total = S * Bv;
        unsigned f0 = (unsigned)zb * ZPB;
        const float4 zf = make_float4(0.f, 0.f, 0.f, 0.f);
        if (f0 < total) {
            unsigned bA = f0 / S, bB = (min(f0 + ZPB, total) - 1) / S;
            if (bA == bB) {  // fast path: whole block inside one slab
                float4* base = out4 + ((long)bA * TL + zstart) * VD - (long)bA * S;
#pragma unroll
                for (int it = 0; it < ZPB / NTHR; ++it) {
                    unsigned f = f0 + tid + it * NTHR;
                    if (f < total) __stcs(base + f, zf);
                }
            } else {
#pragma unroll
                for (int it = 0; it < ZPB / NTHR; ++it) {
                    unsigned f = f0 + tid + it * NTHR;
                    if (f >= total) break;
                    unsigned b = f / S, o = f - b * S;
                    __stcs(out4 + ((long)b * TL + zstart) * VD + o, zf);
                }
            }
        }
    } else {
        // Gather-copy for p in [0, zstart) (always valid: every duration >= 8
        // implies g_total >= GMIN >= zstart). Wait for the scan's flag first.
        int cb = bid - mlpN - nbz;
        if (tid == 0) {
            while (atomicAdd(&g_ready, 0) == 0) __nanosleep(64);
        }
        __syncthreads();
        __threadfence();

        long p0 = (long)cb * CPP;
        __shared__ int s_idx[CPP];
        __shared__ int s_ok[CPP];
        if (tid < CPP) {
            long p = p0 + tid;
            // searchsorted(cum, p, side="right") == upper_bound
            int lo = 0, hi = Tv;
            while (lo < hi) {
                int mid = (lo + hi) >> 1;
                if ((long)g_cum[mid] <= p) lo = mid + 1; else hi = mid;
            }
            s_idx[tid] = (lo < Tv) ? lo : (Tv - 1);
            s_ok[tid]  = (p < zstart);
        }
        __syncthreads();

        const int b  = warp & 3;
        const int h0 = (warp >> 2) * 32;     // 32 positions per warp
        const float4* __restrict__ xb = x4 + (long)b * Tv * VD + lane;
        float4* __restrict__ ob = out4 + (long)b * TL * VD + lane;

        // Run-length dedup: consecutive positions repeat the same source row
        // (every duration >= 8), so load each distinct row once into regs
        // (~4 loads per 32 positions) and issue the ~24 stores of each run
        // back-to-back with NO load dependency.
        int prev = -1;
        float4 v0, v1, v2;
#pragma unroll 4
        for (int i = 0; i < 32; ++i) {
            int pl = h0 + i;
            if (!s_ok[pl]) continue;
            int idx = s_idx[pl];                 // warp-uniform
            if (idx != prev) {
                const float4* src = xb + (long)idx * VD;
                v0 = __ldg(src);
                v1 = __ldg(src + 32);
                v2 = __ldg(src + 64);
                prev = idx;
            }
            float4* dst = ob + (p0 + pl) * VD;
            __stcs(dst,      v0);
            __stcs(dst + 32, v1);
            __stcs(dst + 64, v2);
        }
    }

    // ---- Epilogue: last finishing block does overflow copy + state reset ----
    __shared__ int s_last;
    __syncthreads();
    if (tid == 0) {
        __threadfence();
        s_last = (atomicAdd(&g_done, 1) == (int)gridDim.x - 1);
    }
    __syncthreads();
    if (!s_last) return;
    __threadfence();

    // Overflow region [zstart, min(g_total, TL)) — empty when all durations
    // clamp to MIN_DUR (g_total == GMIN == zstart). Generic fallback path.
    long total = (long)g_total; if (total > TL) total = TL;
    const int b = warp & 3;
    for (long p = zstart + (warp >> 2); p < total; p += 2) {
        int lo = 0, hi = Tv;
        while (lo < hi) {
            int mid = (lo + hi) >> 1;
            if ((long)g_cum[mid] <= p) lo = mid + 1; else hi = mid;
        }
        int idx = (lo < Tv) ? lo : (Tv - 1);
        const float4* src = x4 + ((long)b * Tv + idx) * VD + lane;
        float4* dst = out4 + ((long)b * TL + p) * VD + lane;
        __stcs(dst,      __ldg(src));
        __stcs(dst + 32, __ldg(src + 32));
        __stcs(dst + 64, __ldg(src + 64));
    }
    __syncthreads();
    if (tid == 0) {
        g_cnt = 0; g_ready = 0; g_done = 0;   // reset for next graph replay
        __threadfence();
    }
}

extern "C" void kernel_launch(void* const* d_in, const int* in_sizes, int n_in,
                              void* d_out, int out_size)
{
    const float* x  = (const float*)d_in[0];
    const float* w1 = (const float*)d_in[1];
    const float* b1 = (const float*)d_in[2];
    const float* w2 = (const float*)d_in[3];
    const float* b2 = (const float*)d_in[4];
    float* out = (float*)d_out;

    const int SMEM_DYN = (MROWS * Dv + 2 * KC * Hv) * sizeof(float); // 72KB

    static bool attr_done = false;
    if (!attr_done) {
        cudaFuncSetAttribute(fused_kernel,
            cudaFuncAttributeMaxDynamicSharedMemorySize, SMEM_DYN);
        attr_done = true;
    }

    // Output layout: expanded (Bv, TL, Dv) then duration_pred (Bv, Tv).
    long osz = (long)out_size;
    long TL, tail_off;
    if (osz % ((long)Bv * Dv) == 0) {          // no duration tail in output
        TL = osz / ((long)Bv * Dv);
        tail_off = -1;
    } else {
        TL = (osz - (long)Bv * Tv) / ((long)Bv * Dv);
        tail_off = (long)Bv * TL * Dv;
    }
    long zstart = (long)GMIN < TL ? (long)GMIN : TL;  // zeros for p >= zstart

    long zf4 = (TL - zstart) * VD * Bv;                // float4 to zero
    int nbz  = (int)((zf4 + ZPB - 1) / ZPB);
    int nbc  = (int)((zstart + CPP - 1) / CPP);
    int mlpN = NB0 + ((tail_off >= 0) ? NB13 : 0);

    fused_kernel<<<mlpN + nbz + nbc, NTHR, SMEM_DYN>>>(x, w1, b1, w2, b2, out,
                                                       TL, tail_off, zstart,
                                                       mlpN, nbz);
}

// round 15
// speedup vs baseline: 1.0332x; 1.0332x over previous
#include <cuda_runtime.h>
#include <math.h>
#include <stdint.h>

// Shapes fixed by the problem definition.
#define Bv 4
#define Tv 2048
#define Dv 384
#define Hv 192
#define VD (Dv/4)     // 96 float4 per row
#define MROWS 32      // rows per MLP block (8 warps x 4 rows)
#define NB0 (Tv/MROWS)          // 64 batch-0 MLP blocks
#define NB13 ((Bv-1)*Tv/MROWS)  // 192 MLP blocks for batches 1..3
#define KC 16         // k-tile rows (double buffered)
#define NTILE (Dv/KC) // 24
#define GMIN (8*Tv)   // guaranteed minimum total length (MIN_DUR=8)
#define CPP 32        // output positions per copy block (empirical optimum)
#define ZPB 6144      // float4 per zero block (256 thr x 24)
#define NTHR 256

// Scratch (no allocs allowed).
__device__ float g_dur[Tv];
__device__ int   g_cum[Tv];
__device__ int   g_total;
__device__ int   g_cnt;    // batch-0 completion counter  (reset by last block)
__device__ int   g_ready;  // scan-done flag              (reset by last block)
__device__ int   g_done;   // all-blocks completion count (reset by last block)

#define FMA_F32X2(d, a, b, c) \
    asm("fma.rn.f32x2 %0, %1, %2, %3;" : "=l"(d) : "l"(a), "l"(b), "l"(c))
#define PACK_DUP(out, v) \
    asm("mov.b64 %0, {%1, %1};" : "=l"(out) : "r"(v))
#define UNPACK2(lo, hi, in) \
    asm("mov.b64 {%0, %1}, %2;" : "=r"(lo), "=r"(hi) : "l"(in))

#define CP16(dst_u32, src_ptr) \
    asm volatile("cp.async.cg.shared.global [%0], [%1], 16;\n" :: "r"(dst_u32), "l"(src_ptr))
#define CP_COMMIT() asm volatile("cp.async.commit_group;\n")
#define CP_WAIT(n)  asm volatile("cp.async.wait_group %0;\n" :: "n"(n))

__device__ __forceinline__ uint32_t smem_u32(const void* p) {
    return (uint32_t)__cvta_generic_to_shared(p);
}

__device__ __forceinline__ float duration_of(float z) {
    // softplus -> clamp to MIN_DUR=8 -> round (nearest-even, matching jnp.round)
    float sp = (z > 20.f) ? z : log1pf(expf(z));
    return rintf(fmaxf(sp, 8.f));
}

// MLP for MROWS=32 rows starting at row0 (8 warps, 4 rows/warp).
// w1 streamed via cp.async double-buffered KC=16 tiles; x tile loaded once.
// Packed fma.rn.f32x2 accumulation. (Proven since R4 — unchanged.)
__device__ __forceinline__ void mlp_block(
    const float* __restrict__ x, const float* __restrict__ w1,
    const float* __restrict__ b1, const float* __restrict__ w2,
    const float* __restrict__ b2, int row0,
    float* smem, float* __restrict__ out_tail)
{
    float* s_x = smem;                 // [MROWS][Dv]   48KB
    float* s_w = smem + MROWS * Dv;    // [2][KC][Hv]   24KB

    const int tid  = threadIdx.x;
    const int lane = tid & 31;
    const int warp = tid >> 5;
    const int rb   = warp * 4;

    {
        const float4* __restrict__ xg = (const float4*)(x + (long)row0 * Dv);
        uint32_t sx = smem_u32(s_x);
#pragma unroll
        for (int i = tid; i < MROWS * Dv / 4; i += NTHR)
            CP16(sx + (uint32_t)i * 16u, xg + i);
        CP_COMMIT();
    }
    {
        const float4* __restrict__ wg = (const float4*)w1;
        uint32_t sw = smem_u32(s_w);
#pragma unroll
        for (int i = tid; i < KC * Hv / 4; i += NTHR)
            CP16(sw + (uint32_t)i * 16u, wg + i);
        CP_COMMIT();
    }

    uint64_t acc[4][3];
#pragma unroll
    for (int r = 0; r < 4; ++r)
#pragma unroll
        for (int m = 0; m < 3; ++m) acc[r][m] = 0ull;

    for (int t = 0; t < NTILE; ++t) {
        if (t + 1 < NTILE) {
            const float4* __restrict__ wg =
                (const float4*)(w1 + (long)(t + 1) * KC * Hv);
            uint32_t sw = smem_u32(s_w + ((t + 1) & 1) * KC * Hv);
#pragma unroll
            for (int i = tid; i < KC * Hv / 4; i += NTHR)
                CP16(sw + (uint32_t)i * 16u, wg + i);
            CP_COMMIT();
            CP_WAIT(1);
        } else {
            CP_WAIT(0);
        }
        __syncthreads();

        const float* wb = s_w + (t & 1) * KC * Hv;
#pragma unroll
        for (int k0 = 0; k0 < KC; k0 += 4) {
            float4 xa[4];
#pragma unroll
            for (int r = 0; r < 4; ++r)
                xa[r] = *(const float4*)(s_x + (rb + r) * Dv + t * KC + k0);
#pragma unroll
            for (int kk = 0; kk < 4; ++kk) {
                uint64_t xd[4];
#pragma unroll
                for (int r = 0; r < 4; ++r)
                    PACK_DUP(xd[r], __float_as_uint((&xa[r].x)[kk]));
#pragma unroll
                for (int m = 0; m < 3; ++m) {
                    uint64_t wv = *(const uint64_t*)(wb + (k0 + kk) * Hv
                                                     + 2 * (lane + 32 * m));
#pragma unroll
                    for (int r = 0; r < 4; ++r)
                        FMA_F32X2(acc[r][m], xd[r], wv, acc[r][m]);
                }
            }
        }
        __syncthreads();
    }

    float bz = b2[0];
    float pr[4] = {0.f, 0.f, 0.f, 0.f};
#pragma unroll
    for (int m = 0; m < 3; ++m) {
        int jp = lane + 32 * m;
        float2 bb = *(const float2*)(b1 + 2 * jp);
        float2 ww = *(const float2*)(w2 + 2 * jp);
#pragma unroll
        for (int r = 0; r < 4; ++r) {
            uint32_t lo, hi;
            UNPACK2(lo, hi, acc[r][m]);
            pr[r] += fmaxf(__uint_as_float(lo) + bb.x, 0.f) * ww.x
                   + fmaxf(__uint_as_float(hi) + bb.y, 0.f) * ww.y;
        }
    }
#pragma unroll
    for (int off = 16; off > 0; off >>= 1)
#pragma unroll
        for (int r = 0; r < 4; ++r)
            pr[r] += __shfl_xor_sync(0xffffffffu, pr[r], off);
    if (lane == 0) {
#pragma unroll
        for (int r = 0; r < 4; ++r) {
            int row = row0 + rb + r;
            float d = duration_of(pr[r] + bz);
            if (out_tail) out_tail[row] = d;
            if (row < Tv) g_dur[row] = d;
        }
    }
}

// Fused kernel. Grid layout (bid order = dispatch order) — R9/R12 proven:
//  [0, NB0)            batch-0 MLP; last finisher scans g_dur -> g_cum,
//                      g_total, then sets g_ready (fence-ordered)
//  [NB0, mlpN)         MLP for batches 1..3 (duration_pred tail only)
//  [mlpN, mlpN+nbz)    zero-fill out[b][zstart..TL][:]  (flat, contiguous)
//  [mlpN+nbz, ...)     gather-copy p in [0, zstart); waits on g_ready
//                      (dispatched ~40us in; flag set ~8us in, so no stall)
// Epilogue (all blocks): increment g_done; the final finisher copies the
// overflow [zstart, g_total) over the zeros — ordered after ALL zero/copy
// blocks, so no race; empty when g_total == GMIN — and resets replay state.
__global__ __launch_bounds__(NTHR)
void fused_kernel(const float* __restrict__ x, const float* __restrict__ w1,
                  const float* __restrict__ b1, const float* __restrict__ w2,
                  const float* __restrict__ b2, float* __restrict__ out,
                  long TL, long tail_off, long zstart, int mlpN, int nbz)
{
    extern __shared__ float smem[];
    const int tid  = threadIdx.x;
    const int lane = tid & 31;
    const int warp = tid >> 5;
    int bid = (int)blockIdx.x;
    float4* __restrict__ out4 = (float4*)out;
    const float4* __restrict__ x4 = (const float4*)x;

    if (bid < mlpN) {
        int row0 = (bid < NB0) ? bid * MROWS : Tv + (bid - NB0) * MROWS;
        mlp_block(x, w1, b1, w2, b2, row0, smem,
                  tail_off >= 0 ? out + tail_off : nullptr);
        if (bid < NB0) {
            // Batch-0 blocks: last finisher performs the scan + publishes.
            __shared__ int s_go;
            __syncthreads();
            if (tid == 0) {
                __threadfence();
                s_go = (atomicAdd(&g_cnt, 1) == NB0 - 1);
            }
            __syncthreads();
            if (s_go) {
                __threadfence();
                int* s_sum = (int*)smem;
                int loc[8]; int s = 0;
#pragma unroll
                for (int i = 0; i < 8; ++i) {
                    loc[i] = (int)g_dur[tid * 8 + i]; s += loc[i];
                }
                s_sum[tid] = s;
                __syncthreads();
#pragma unroll
                for (int off = 1; off < 256; off <<= 1) {
                    int v = (tid >= off) ? s_sum[tid - off] : 0;
                    __syncthreads();
                    s_sum[tid] += v;
                    __syncthreads();
                }
                int run = (tid > 0) ? s_sum[tid - 1] : 0;
#pragma unroll
                for (int i = 0; i < 8; ++i) {
                    run += loc[i]; g_cum[tid * 8 + i] = run;
                }
                if (tid == 255) g_total = run;
                __syncthreads();
                if (tid == 0) {
                    __threadfence();
                    atomicExch(&g_ready, 1);
                }
            }
        }
    } else if (bid < mlpN + nbz) {
        // Zero-fill: flat float4 index space over Bv slabs out[b][zstart..TL][:].
        int zb = bid - mlpN;
        unsigned S = (unsigned)((TL - zstart) * VD);   // f4 per slab
        unsigned total = S * Bv;
        unsigned f0 = (unsigned)zb * ZPB;
        const float4 zf = make_float4(0.f, 0.f, 0.f, 0.f);
        if (f0 < total) {
            unsigned bA = f0 / S, bB = (min(f0 + ZPB, total) - 1) / S;
            if (bA == bB) {  // fast path: whole block inside one slab
                float4* base = out4 + ((long)bA * TL + zstart) * VD - (long)bA * S;
#pragma unroll
                for (int it = 0; it < ZPB / NTHR; ++it) {
                    unsigned f = f0 + tid + it * NTHR;
                    if (f < total) __stcs(base + f, zf);
                }
            } else {
#pragma unroll
                for (int it = 0; it < ZPB / NTHR; ++it) {
                    unsigned f = f0 + tid + it * NTHR;
                    if (f >= total) break;
                    unsigned b = f / S, o = f - b * S;
                    __stcs(out4 + ((long)b * TL + zstart) * VD + o, zf);
                }
            }
        }
    } else {
        // Gather-copy for p in [0, zstart) (always valid: every duration >= 8
        // implies g_total >= GMIN >= zstart). Wait for the scan's flag first.
        int cb = bid - mlpN - nbz;
        if (tid == 0) {
            while (atomicAdd(&g_ready, 0) == 0) __nanosleep(64);
        }
        __syncthreads();
        __threadfence();

        long p0 = (long)cb * CPP;
        __shared__ int s_idx[CPP];
        __shared__ int s_ok[CPP];
        if (tid < CPP) {
            long p = p0 + tid;
            // searchsorted(cum, p, side="right") == upper_bound
            int lo = 0, hi = Tv;
            while (lo < hi) {
                int mid = (lo + hi) >> 1;
                if ((long)g_cum[mid] <= p) lo = mid + 1; else hi = mid;
            }
            s_idx[tid] = (lo < Tv) ? lo : (Tv - 1);
            s_ok[tid]  = (p < zstart);
        }
        __syncthreads();

        const int b  = warp & 3;
        const int h0 = (warp >> 2) * 16;     // 16 positions per warp
        const float4* __restrict__ xb = x4 + (long)b * Tv * VD + lane;
        float4* __restrict__ ob = out4 + (long)b * TL * VD + lane;

        // Run-length dedup: consecutive positions repeat the same source row
        // (every duration >= 8), so load each distinct row once into regs
        // and issue its stores back-to-back with NO load dependency.
        int prev = -1;
        float4 v0, v1, v2;
#pragma unroll 4
        for (int i = 0; i < 16; ++i) {
            int pl = h0 + i;
            if (!s_ok[pl]) continue;
            int idx = s_idx[pl];                 // warp-uniform
            if (idx != prev) {
                const float4* src = xb + (long)idx * VD;
                v0 = __ldg(src);
                v1 = __ldg(src + 32);
                v2 = __ldg(src + 64);
                prev = idx;
            }
            float4* dst = ob + (p0 + pl) * VD;
            __stcs(dst,      v0);
            __stcs(dst + 32, v1);
            __stcs(dst + 64, v2);
        }
    }

    // ---- Epilogue: last finishing block does overflow copy + state reset ----
    __shared__ int s_last;
    __syncthreads();
    if (tid == 0) {
        __threadfence();
        s_last = (atomicAdd(&g_done, 1) == (int)gridDim.x - 1);
    }
    __syncthreads();
    if (!s_last) return;
    __threadfence();

    // Overflow region [zstart, min(g_total, TL)) — empty when all durations
    // clamp to MIN_DUR (g_total == GMIN == zstart). Generic fallback path.
    long total = (long)g_total; if (total > TL) total = TL;
    const int b = warp & 3;
    for (long p = zstart + (warp >> 2); p < total; p += 2) {
        int lo = 0, hi = Tv;
        while (lo < hi) {
            int mid = (lo + hi) >> 1;
            if ((long)g_cum[mid] <= p) lo = mid + 1; else hi = mid;
        }
        int idx = (lo < Tv) ? lo : (Tv - 1);
        const float4* src = x4 + ((long)b * Tv + idx) * VD + lane;
        float4* dst = out4 + ((long)b * TL + p) * VD + lane;
        __stcs(dst,      __ldg(src));
        __stcs(dst + 32, __ldg(src + 32));
        __stcs(dst + 64, __ldg(src + 64));
    }
    __syncthreads();
    if (tid == 0) {
        g_cnt = 0; g_ready = 0; g_done = 0;   // reset for next graph replay
        __threadfence();
    }
}

extern "C" void kernel_launch(void* const* d_in, const int* in_sizes, int n_in,
                              void* d_out, int out_size)
{
    const float* x  = (const float*)d_in[0];
    const float* w1 = (const float*)d_in[1];
    const float* b1 = (const float*)d_in[2];
    const float* w2 = (const float*)d_in[3];
    const float* b2 = (const float*)d_in[4];
    float* out = (float*)d_out;

    const int SMEM_DYN = (MROWS * Dv + 2 * KC * Hv) * sizeof(float); // 72KB

    static bool attr_done = false;
    if (!attr_done) {
        cudaFuncSetAttribute(fused_kernel,
            cudaFuncAttributeMaxDynamicSharedMemorySize, SMEM_DYN);
        attr_done = true;
    }

    // Output layout: expanded (Bv, TL, Dv) then duration_pred (Bv, Tv).
    long osz = (long)out_size;
    long TL, tail_off;
    if (osz % ((long)Bv * Dv) == 0) {          // no duration tail in output
        TL = osz / ((long)Bv * Dv);
        tail_off = -1;
    } else {
        TL = (osz - (long)Bv * Tv) / ((long)Bv * Dv);
        tail_off = (long)Bv * TL * Dv;
    }
    long zstart = (long)GMIN < TL ? (long)GMIN : TL;  // zeros for p >= zstart

    long zf4 = (TL - zstart) * VD * Bv;                // float4 to zero
    int nbz  = (int)((zf4 + ZPB - 1) / ZPB);
    int nbc  = (int)((zstart + CPP - 1) / CPP);
    int mlpN = NB0 + ((tail_off >= 0) ? NB13 : 0);

    fused_kernel<<<mlpN + nbz + nbc, NTHR, SMEM_DYN>>>(x, w1, b1, w2, b2, out,
                                                       TL, tail_off, zstart,
                                                       mlpN, nbz);
}

// round 16
// speedup vs baseline: 1.0547x; 1.0208x over previous
#include <cuda_runtime.h>
#include <math.h>
#include <stdint.h>

// Shapes fixed by the problem definition.
#define Bv 4
#define Tv 2048
#define Dv 384
#define Hv 192
#define VD (Dv/4)     // 96 float4 per row
#define MROWS 32      // rows per MLP block (8 warps x 4 rows)
#define NB0 (Tv/MROWS)          // 64 batch-0 MLP blocks
#define NB13 ((Bv-1)*Tv/MROWS)  // 192 MLP blocks for batches 1..3
#define KC 16         // k-tile rows (double buffered)
#define NTILE (Dv/KC) // 24
#define GMIN (8*Tv)   // guaranteed minimum total length (MIN_DUR=8)
#define CPP 32        // output positions per copy block (empirical optimum)
#define ZPB 6144      // float4 per zero block (256 thr x 24)
#define NTHR 256

// Scratch (no allocs allowed).
__device__ float g_dur[Tv];
__device__ int   g_cum[Tv];
__device__ int   g_total;
__device__ int   g_cnt;    // batch-0 completion counter  (reset by last block)
__device__ int   g_ready;  // scan-done flag              (reset by last block)
__device__ int   g_done;   // all-blocks completion count (reset by last block)

#define FMA_F32X2(d, a, b, c) \
    asm("fma.rn.f32x2 %0, %1, %2, %3;" : "=l"(d) : "l"(a), "l"(b), "l"(c))
#define PACK_DUP(out, v) \
    asm("mov.b64 %0, {%1, %1};" : "=l"(out) : "r"(v))
#define UNPACK2(lo, hi, in) \
    asm("mov.b64 {%0, %1}, %2;" : "=r"(lo), "=r"(hi) : "l"(in))

#define CP16(dst_u32, src_ptr) \
    asm volatile("cp.async.cg.shared.global [%0], [%1], 16;\n" :: "r"(dst_u32), "l"(src_ptr))
#define CP_COMMIT() asm volatile("cp.async.commit_group;\n")
#define CP_WAIT(n)  asm volatile("cp.async.wait_group %0;\n" :: "n"(n))

__device__ __forceinline__ uint32_t smem_u32(const void* p) {
    return (uint32_t)__cvta_generic_to_shared(p);
}

__device__ __forceinline__ float duration_of(float z) {
    // softplus -> clamp to MIN_DUR=8 -> round (nearest-even, matching jnp.round)
    float sp = (z > 20.f) ? z : log1pf(expf(z));
    return rintf(fmaxf(sp, 8.f));
}

// MLP for MROWS=32 rows starting at row0 (8 warps, 4 rows/warp).
// w1 streamed via cp.async double-buffered KC=16 tiles; x tile loaded once.
// Packed fma.rn.f32x2 accumulation. (Proven since R4 — unchanged.)
__device__ __forceinline__ void mlp_block(
    const float* __restrict__ x, const float* __restrict__ w1,
    const float* __restrict__ b1, const float* __restrict__ w2,
    const float* __restrict__ b2, int row0,
    float* smem, float* __restrict__ out_tail)
{
    float* s_x = smem;                 // [MROWS][Dv]   48KB
    float* s_w = smem + MROWS * Dv;    // [2][KC][Hv]   24KB

    const int tid  = threadIdx.x;
    const int lane = tid & 31;
    const int warp = tid >> 5;
    const int rb   = warp * 4;

    {
        const float4* __restrict__ xg = (const float4*)(x + (long)row0 * Dv);
        uint32_t sx = smem_u32(s_x);
#pragma unroll
        for (int i = tid; i < MROWS * Dv / 4; i += NTHR)
            CP16(sx + (uint32_t)i * 16u, xg + i);
        CP_COMMIT();
    }
    {
        const float4* __restrict__ wg = (const float4*)w1;
        uint32_t sw = smem_u32(s_w);
#pragma unroll
        for (int i = tid; i < KC * Hv / 4; i += NTHR)
            CP16(sw + (uint32_t)i * 16u, wg + i);
        CP_COMMIT();
    }

    uint64_t acc[4][3];
#pragma unroll
    for (int r = 0; r < 4; ++r)
#pragma unroll
        for (int m = 0; m < 3; ++m) acc[r][m] = 0ull;

    for (int t = 0; t < NTILE; ++t) {
        if (t + 1 < NTILE) {
            const float4* __restrict__ wg =
                (const float4*)(w1 + (long)(t + 1) * KC * Hv);
            uint32_t sw = smem_u32(s_w + ((t + 1) & 1) * KC * Hv);
#pragma unroll
            for (int i = tid; i < KC * Hv / 4; i += NTHR)
                CP16(sw + (uint32_t)i * 16u, wg + i);
            CP_COMMIT();
            CP_WAIT(1);
        } else {
            CP_WAIT(0);
        }
        __syncthreads();

        const float* wb = s_w + (t & 1) * KC * Hv;
#pragma unroll
        for (int k0 = 0; k0 < KC; k0 += 4) {
            float4 xa[4];
#pragma unroll
            for (int r = 0; r < 4; ++r)
                xa[r] = *(const float4*)(s_x + (rb + r) * Dv + t * KC + k0);
#pragma unroll
            for (int kk = 0; kk < 4; ++kk) {
                uint64_t xd[4];
#pragma unroll
                for (int r = 0; r < 4; ++r)
                    PACK_DUP(xd[r], __float_as_uint((&xa[r].x)[kk]));
#pragma unroll
                for (int m = 0; m < 3; ++m) {
                    uint64_t wv = *(const uint64_t*)(wb + (k0 + kk) * Hv
                                                     + 2 * (lane + 32 * m));
#pragma unroll
                    for (int r = 0; r < 4; ++r)
                        FMA_F32X2(acc[r][m], xd[r], wv, acc[r][m]);
                }
            }
        }
        __syncthreads();
    }

    float bz = b2[0];
    float pr[4] = {0.f, 0.f, 0.f, 0.f};
#pragma unroll
    for (int m = 0; m < 3; ++m) {
        int jp = lane + 32 * m;
        float2 bb = *(const float2*)(b1 + 2 * jp);
        float2 ww = *(const float2*)(w2 + 2 * jp);
#pragma unroll
        for (int r = 0; r < 4; ++r) {
            uint32_t lo, hi;
            UNPACK2(lo, hi, acc[r][m]);
            pr[r] += fmaxf(__uint_as_float(lo) + bb.x, 0.f) * ww.x
                   + fmaxf(__uint_as_float(hi) + bb.y, 0.f) * ww.y;
        }
    }
#pragma unroll
    for (int off = 16; off > 0; off >>= 1)
#pragma unroll
        for (int r = 0; r < 4; ++r)
            pr[r] += __shfl_xor_sync(0xffffffffu, pr[r], off);
    if (lane == 0) {
#pragma unroll
        for (int r = 0; r < 4; ++r) {
            int row = row0 + rb + r;
            float d = duration_of(pr[r] + bz);
            if (out_tail) out_tail[row] = d;
            if (row < Tv) g_dur[row] = d;
        }
    }
}

// Zero-fill one ZPB-sized chunk of the flat float4 index space over the Bv
// slabs out[b][zstart..TL][:]. (Proven store pattern — unchanged.)
__device__ __forceinline__ void zero_blk(
    float4* __restrict__ out4, long TL, long zstart, int zidx, int tid)
{
    unsigned S = (unsigned)((TL - zstart) * VD);   // f4 per slab
    unsigned total = S * Bv;
    unsigned f0 = (unsigned)zidx * ZPB;
    const float4 zf = make_float4(0.f, 0.f, 0.f, 0.f);
    if (f0 >= total) return;
    unsigned bA = f0 / S, bB = (min(f0 + ZPB, total) - 1) / S;
    if (bA == bB) {  // fast path: whole block inside one slab
        float4* base = out4 + ((long)bA * TL + zstart) * VD - (long)bA * S;
#pragma unroll
        for (int it = 0; it < ZPB / NTHR; ++it) {
            unsigned f = f0 + tid + it * NTHR;
            if (f < total) __stcs(base + f, zf);
        }
    } else {
#pragma unroll
        for (int it = 0; it < ZPB / NTHR; ++it) {
            unsigned f = f0 + tid + it * NTHR;
            if (f >= total) break;
            unsigned b = f / S, o = f - b * S;
            __stcs(out4 + ((long)b * TL + zstart) * VD + o, zf);
        }
    }
}

// Fused kernel. Grid layout (bid order = dispatch order):
//  [0, NB0)            batch-0 MLP; last finisher scans g_dur -> g_cum,
//                      g_total, sets g_ready (fence-ordered); THEN the block
//                      zero-fills chunk 'bid' (store work after compute)
//  [NB0, mlpN)         MLP for batches 1..3 + zero-fill chunk 'bid'
//  [mlpN, zEnd)        dedicated zero-fill, chunk 'bid' (same flat index
//                      space — chunks 0..mlpN-1 belong to the MLP blocks)
//  [zEnd, zEnd+nbc)    gather-copy p in [0, zstart); waits on g_ready
//                      (dispatched ~40us in; flag set ~8us in, so no stall)
// Zero bytes/pattern identical to R12 — chunks 0..mlpN-1 just moved into the
// MLP blocks' tails, shrinking the grid by mlpN blocks and making every block
// a store-issuing block. Epilogue: last finishing block copies overflow
// [zstart, g_total) (empty when all durations clamp) and resets replay state.
__global__ __launch_bounds__(NTHR)
void fused_kernel(const float* __restrict__ x, const float* __restrict__ w1,
                  const float* __restrict__ b1, const float* __restrict__ w2,
                  const float* __restrict__ b2, float* __restrict__ out,
                  long TL, long tail_off, long zstart, int mlpN, int zEnd)
{
    extern __shared__ float smem[];
    const int tid  = threadIdx.x;
    const int lane = tid & 31;
    const int warp = tid >> 5;
    int bid = (int)blockIdx.x;
    float4* __restrict__ out4 = (float4*)out;
    const float4* __restrict__ x4 = (const float4*)x;

    if (bid < mlpN) {
        int row0 = (bid < NB0) ? bid * MROWS : Tv + (bid - NB0) * MROWS;
        mlp_block(x, w1, b1, w2, b2, row0, smem,
                  tail_off >= 0 ? out + tail_off : nullptr);
        if (bid < NB0) {
            // Batch-0 blocks: last finisher performs the scan + publishes.
            __shared__ int s_go;
            __syncthreads();
            if (tid == 0) {
                __threadfence();
                s_go = (atomicAdd(&g_cnt, 1) == NB0 - 1);
            }
            __syncthreads();
            if (s_go) {
                __threadfence();
                int* s_sum = (int*)smem;
                int loc[8]; int s = 0;
#pragma unroll
                for (int i = 0; i < 8; ++i) {
                    loc[i] = (int)g_dur[tid * 8 + i]; s += loc[i];
                }
                s_sum[tid] = s;
                __syncthreads();
#pragma unroll
                for (int off = 1; off < 256; off <<= 1) {
                    int v = (tid >= off) ? s_sum[tid - off] : 0;
                    __syncthreads();
                    s_sum[tid] += v;
                    __syncthreads();
                }
                int run = (tid > 0) ? s_sum[tid - 1] : 0;
#pragma unroll
                for (int i = 0; i < 8; ++i) {
                    run += loc[i]; g_cum[tid * 8 + i] = run;
                }
                if (tid == 255) g_total = run;
                __syncthreads();
                if (tid == 0) {
                    __threadfence();
                    atomicExch(&g_ready, 1);
                }
            }
        }
        // After compute (and scan publish), contribute store work: chunk bid.
        zero_blk(out4, TL, zstart, bid, tid);
    } else if (bid < zEnd) {
        zero_blk(out4, TL, zstart, bid, tid);   // chunks mlpN..zEnd-1
    } else {
        // Gather-copy for p in [0, zstart) (always valid: every duration >= 8
        // implies g_total >= GMIN >= zstart). Wait for the scan's flag first.
        int cb = bid - zEnd;
        if (tid == 0) {
            while (atomicAdd(&g_ready, 0) == 0) __nanosleep(64);
        }
        __syncthreads();
        __threadfence();

        long p0 = (long)cb * CPP;
        __shared__ int s_idx[CPP];
        __shared__ int s_ok[CPP];
        if (tid < CPP) {
            long p = p0 + tid;
            // searchsorted(cum, p, side="right") == upper_bound
            int lo = 0, hi = Tv;
            while (lo < hi) {
                int mid = (lo + hi) >> 1;
                if ((long)g_cum[mid] <= p) lo = mid + 1; else hi = mid;
            }
            s_idx[tid] = (lo < Tv) ? lo : (Tv - 1);
            s_ok[tid]  = (p < zstart);
        }
        __syncthreads();

        const int b  = warp & 3;
        const int h0 = (warp >> 2) * 16;     // 16 positions per warp
        const float4* __restrict__ xb = x4 + (long)b * Tv * VD + lane;
        float4* __restrict__ ob = out4 + (long)b * TL * VD + lane;

        // Run-length dedup: consecutive positions repeat the same source row
        // (every duration >= 8), so load each distinct row once into regs
        // and issue its stores back-to-back with NO load dependency.
        int prev = -1;
        float4 v0, v1, v2;
#pragma unroll 4
        for (int i = 0; i < 16; ++i) {
            int pl = h0 + i;
            if (!s_ok[pl]) continue;
            int idx = s_idx[pl];                 // warp-uniform
            if (idx != prev) {
                const float4* src = xb + (long)idx * VD;
                v0 = __ldg(src);
                v1 = __ldg(src + 32);
                v2 = __ldg(src + 64);
                prev = idx;
            }
            float4* dst = ob + (p0 + pl) * VD;
            __stcs(dst,      v0);
            __stcs(dst + 32, v1);
            __stcs(dst + 64, v2);
        }
    }

    // ---- Epilogue: last finishing block does overflow copy + state reset ----
    __shared__ int s_last;
    __syncthreads();
    if (tid == 0) {
        __threadfence();
        s_last = (atomicAdd(&g_done, 1) == (int)gridDim.x - 1);
    }
    __syncthreads();
    if (!s_last) return;
    __threadfence();

    // Overflow region [zstart, min(g_total, TL)) — empty when all durations
    // clamp to MIN_DUR (g_total == GMIN == zstart). Generic fallback path.
    long total = (long)g_total; if (total > TL) total = TL;
    const int b = warp & 3;
    for (long p = zstart + (warp >> 2); p < total; p += 2) {
        int lo = 0, hi = Tv;
        while (lo < hi) {
            int mid = (lo + hi) >> 1;
            if ((long)g_cum[mid] <= p) lo = mid + 1; else hi = mid;
        }
        int idx = (lo < Tv) ? lo : (Tv - 1);
        const float4* src = x4 + ((long)b * Tv + idx) * VD + lane;
        float4* dst = out4 + ((long)b * TL + p) * VD + lane;
        __stcs(dst,      __ldg(src));
        __stcs(dst + 32, __ldg(src + 32));
        __stcs(dst + 64, __ldg(src + 64));
    }
    __syncthreads();
    if (tid == 0) {
        g_cnt = 0; g_ready = 0; g_done = 0;   // reset for next graph replay
        __threadfence();
    }
}

extern "C" void kernel_launch(void* const* d_in, const int* in_sizes, int n_in,
                              void* d_out, int out_size)
{
    const float* x  = (const float*)d_in[0];
    const float* w1 = (const float*)d_in[1];
    const float* b1 = (const float*)d_in[2];
    const float* w2 = (const float*)d_in[3];
    const float* b2 = (const float*)d_in[4];
    float* out = (float*)d_out;

    const int SMEM_DYN = (MROWS * Dv + 2 * KC * Hv) * sizeof(float); // 72KB

    static bool attr_done = false;
    if (!attr_done) {
        cudaFuncSetAttribute(fused_kernel,
            cudaFuncAttributeMaxDynamicSharedMemorySize, SMEM_DYN);
        attr_done = true;
    }

    // Output layout: expanded (Bv, TL, Dv) then duration_pred (Bv, Tv).
    long osz = (long)out_size;
    long TL, tail_off;
    if (osz % ((long)Bv * Dv) == 0) {          // no duration tail in output
        TL = osz / ((long)Bv * Dv);
        tail_off = -1;
    } else {
        TL = (osz - (long)Bv * Tv) / ((long)Bv * Dv);
        tail_off = (long)Bv * TL * Dv;
    }
    long zstart = (long)GMIN < TL ? (long)GMIN : TL;  // zeros for p >= zstart

    long zf4 = (TL - zstart) * VD * Bv;                // float4 to zero
    int nbz  = (int)((zf4 + ZPB - 1) / ZPB);           // total zero chunks
    int nbc  = (int)((zstart + CPP - 1) / CPP);
    int mlpN = NB0 + ((tail_off >= 0) ? NB13 : 0);

    // MLP blocks take zero chunks 0..mlpN-1; dedicated blocks the rest.
    int zEnd = (nbz > mlpN) ? nbz : mlpN;

    fused_kernel<<<zEnd + nbc, NTHR, SMEM_DYN>>>(x, w1, b1, w2, b2, out,
                                                 TL, tail_off, zstart,
                                                 mlpN, zEnd);
}